// round 7
// baseline (speedup 1.0000x reference)
#include <cuda_runtime.h>
#include <cuda_bf16.h>
#include <cuda_fp8.h>
#include <cstdint>
#include <cstddef>

#define DEV_INLINE __device__ __forceinline__

// ---------------- problem constants (fixed shapes) ----------------
constexpr int N_ROWS = 4096;
constexpr int DIM    = 512;              // elements == bytes in fp8
constexpr int NCLS   = 50000;
constexpr float S_SCALE    = 30.0f;
constexpr float QSCALE     = 16.0f;      // quantization pre-scale (both operands)
constexpr float INV_QQ     = 1.0f / 256.0f;   // 1/(16*16)
constexpr float MARGIN_COS = 0.9210609940028851f;  // cos(0.4)
constexpr float MARGIN_SIN = 0.3894183423086505f;  // sin(0.4)

// ---------------- GEMM tiling ----------------
constexpr int BM = 128;
constexpr int BN = 128;
constexpr int BKB = 128;               // K bytes per chunk (128 fp8 = one 128B SW128 row)
constexpr int NKI = DIM / BKB;         // 4 k-iterations
constexpr int NSTAGE = 3;
constexpr int MTILES = N_ROWS / BM;                  // 32
constexpr int NTILES = (NCLS + BN - 1) / BN;         // 391 (last masked)

constexpr uint32_t A_STAGE = BM * 128;               // 16384
constexpr uint32_t B_STAGE = BN * 128;               // 16384
constexpr uint32_t STAGE_BYTES = A_STAGE + B_STAGE;  // 32768
constexpr uint32_t SMEM_EXCL = NSTAGE * STAGE_BYTES;         // 98304
constexpr uint32_t SMEM_TG   = SMEM_EXCL + BM * 4;           // 98816
constexpr uint32_t SMEM_TOTAL = SMEM_TG + BM * 4;            // 99328 (x2 CTA = 199KB)

// ---------------- device scratch (allocation-free rule) ----------------
__device__ uint8_t g_xq[(size_t)N_ROWS * DIM];   // 16*normalized(x), e4m3 (2MB)
__device__ uint8_t g_wq[(size_t)NCLS * DIM];     // 16*W, e4m3 (25.6MB, L2-resident)
__device__ float g_excl[N_ROWS];
__device__ float g_tgt[N_ROWS];
__device__ float g_sum;

// ---------------- helpers ----------------
DEV_INLINE uint32_t smem_u32(const void* p) { return (uint32_t)__cvta_generic_to_shared(p); }
DEV_INLINE uint32_t swz(uint32_t o) { return o ^ ((o >> 3) & 0x70); }

DEV_INLINE void cp16(uint32_t dst, const void* src) {
    asm volatile("cp.async.cg.shared.global [%0], [%1], 16;" :: "r"(dst), "l"(src));
}

DEV_INLINE void ldm_x4(uint32_t& r0, uint32_t& r1, uint32_t& r2, uint32_t& r3,
                       uint32_t addr) {
    asm volatile("ldmatrix.sync.aligned.m8n8.x4.shared.b16 {%0,%1,%2,%3}, [%4];"
                 : "=r"(r0), "=r"(r1), "=r"(r2), "=r"(r3) : "r"(addr));
}

DEV_INLINE void mma_fp8(float* d, const uint32_t* a, uint32_t b0, uint32_t b1) {
    asm volatile(
        "mma.sync.aligned.m16n8k32.row.col.f32.e4m3.e4m3.f32 "
        "{%0,%1,%2,%3}, {%4,%5,%6,%7}, {%8,%9}, {%0,%1,%2,%3};"
        : "+f"(d[0]), "+f"(d[1]), "+f"(d[2]), "+f"(d[3])
        : "r"(a[0]), "r"(a[1]), "r"(a[2]), "r"(a[3]), "r"(b0), "r"(b1));
}

DEV_INLINE uint32_t pack4_e4m3(float a, float b, float c, float d) {
    __nv_fp8x2_storage_t lo = __nv_cvt_float2_to_fp8x2(make_float2(a, b),
                                                       __NV_SATFINITE, __NV_E4M3);
    __nv_fp8x2_storage_t hi = __nv_cvt_float2_to_fp8x2(make_float2(c, d),
                                                       __NV_SATFINITE, __NV_E4M3);
    return (uint32_t)lo | ((uint32_t)hi << 16);
}

// ---------------- kernel 0: zero the loss accumulator ----------------
__global__ void zero_sum_kernel() { g_sum = 0.0f; }

// ---------------- kernel 1: W fp32 -> e4m3 (x16) ----------------
__global__ void conv_w_kernel(const float* __restrict__ W) {
    size_t i = ((size_t)blockIdx.x * blockDim.x + threadIdx.x) * 4;
    float4 v = *reinterpret_cast<const float4*>(W + i);
    *reinterpret_cast<uint32_t*>(g_wq + i) =
        pack4_e4m3(v.x * QSCALE, v.y * QSCALE, v.z * QSCALE, v.w * QSCALE);
}

// ---------------- kernel 2: normalize x rows -> e4m3 (x16), zero excl ----------------
__global__ void prep_x_kernel(const float* __restrict__ x) {
    int row = blockIdx.x * 8 + (threadIdx.x >> 5);
    int lid = threadIdx.x & 31;
    const float4* xr4 = reinterpret_cast<const float4*>(x + (size_t)row * DIM);
    float4 vals[4];
    float s = 0.0f;
#pragma unroll
    for (int j = 0; j < 4; j++) {
        float4 v = xr4[lid + j * 32];
        vals[j] = v;
        s += v.x * v.x + v.y * v.y + v.z * v.z + v.w * v.w;
    }
#pragma unroll
    for (int o = 16; o; o >>= 1) s += __shfl_xor_sync(0xFFFFFFFFu, s, o);
    float rn = rsqrtf(s) * QSCALE;
    uint32_t* outr = reinterpret_cast<uint32_t*>(g_xq + (size_t)row * DIM);
#pragma unroll
    for (int j = 0; j < 4; j++) {
        float4 v = vals[j];
        outr[lid + j * 32] = pack4_e4m3(v.x * rn, v.y * rn, v.z * rn, v.w * rn);
    }
    if (lid == 0) g_excl[row] = 0.0f;   // re-zero on every graph replay
}

// ---------------- kernel 3: FP8 MMA GEMM + fused arcface epilogue ----------------
// BM=128 x BN=128, 8 warps in 2x4 grid, 64x32 warp tiles, 2 CTAs/SM, 3-stage.
__global__ void __launch_bounds__(256, 2)
arc_gemm_kernel(const int* __restrict__ target) {
    extern __shared__ char smem[];
    const uint32_t sb = smem_u32(smem);
    float* s_excl = reinterpret_cast<float*>(smem + SMEM_EXCL);
    int*   s_tg   = reinterpret_cast<int*>(smem + SMEM_TG);

    const int tid = threadIdx.x;
    const int lid = tid & 31;
    const int wid = tid >> 5;
    const int wm  = wid & 1;          // 0..1  (m, 64 rows each)
    const int wn  = wid >> 1;         // 0..3  (n, 32 cols each)
    const int rbase = blockIdx.x * BM;
    const int cbase = blockIdx.y * BN;

    if (tid < BM) {
        s_excl[tid] = 0.0f;
        s_tg[tid]   = target[rbase + tid];
    }

    // cp.async chunking: 16B chunks; chunk = tid + i*256; row = chunk>>3, kb = chunk&7
    const int c_row = tid >> 3;
    const int c_kb  = tid & 7;

    // ldmatrix address components (byte-identical layout to bf16 m16n8k16)
    const uint32_t a_row  = wm * 64 + (lid & 15);
    const uint32_t a_koff = (lid >> 4) * 16;
    const uint32_t b_row  = wn * 32 + (lid & 7) + ((lid >> 4) & 1) * 8;
    const uint32_t b_koff = ((lid >> 3) & 1) * 16;

    float acc[4][4][4];
#pragma unroll
    for (int mt = 0; mt < 4; mt++)
#pragma unroll
        for (int nt = 0; nt < 4; nt++)
#pragma unroll
            for (int j = 0; j < 4; j++) acc[mt][nt][j] = 0.0f;

    // ---- prefetch stages 0 and 1 ----
#pragma unroll
    for (int pk = 0; pk < 2; pk++) {
        const int k0 = pk * BKB;
        const uint32_t sa  = sb + pk * STAGE_BYTES;
        const uint32_t sbb = sa + A_STAGE;
        const uint8_t* xs = g_xq + (size_t)rbase * DIM + k0 + c_kb * 16;
#pragma unroll
        for (int i = 0; i < 4; i++) {
            int row = c_row + i * 32;
            cp16(sa + swz(row * 128 + c_kb * 16), xs + (size_t)row * DIM);
        }
        const uint8_t* ws = g_wq + k0 + c_kb * 16;
#pragma unroll
        for (int i = 0; i < 4; i++) {
            int row = c_row + i * 32;
            int c = cbase + row; c = (c < NCLS) ? c : (NCLS - 1);
            cp16(sbb + swz(row * 128 + c_kb * 16), ws + (size_t)c * DIM);
        }
        asm volatile("cp.async.commit_group;" ::: "memory");
    }

    int stage = 0;
    for (int k = 0; k < NKI; k++) {
        if (k == NKI - 1)
            asm volatile("cp.async.wait_group 0;" ::: "memory");
        else
            asm volatile("cp.async.wait_group 1;" ::: "memory");
        __syncthreads();

        if (k + 2 < NKI) {
            const int ps = (stage + 2 >= NSTAGE) ? stage + 2 - NSTAGE : stage + 2;
            const int k0 = (k + 2) * BKB;
            const uint32_t sa  = sb + ps * STAGE_BYTES;
            const uint32_t sbb = sa + A_STAGE;
            const uint8_t* xs = g_xq + (size_t)rbase * DIM + k0 + c_kb * 16;
#pragma unroll
            for (int i = 0; i < 4; i++) {
                int row = c_row + i * 32;
                cp16(sa + swz(row * 128 + c_kb * 16), xs + (size_t)row * DIM);
            }
            const uint8_t* ws = g_wq + k0 + c_kb * 16;
#pragma unroll
            for (int i = 0; i < 4; i++) {
                int row = c_row + i * 32;
                int c = cbase + row; c = (c < NCLS) ? c : (NCLS - 1);
                cp16(sbb + swz(row * 128 + c_kb * 16), ws + (size_t)c * DIM);
            }
            asm volatile("cp.async.commit_group;" ::: "memory");
        }

        const uint32_t abase = sb + stage * STAGE_BYTES;
        const uint32_t bbase = abase + A_STAGE;
        // ---- compute 128 K-bytes as 4 k-steps of k32 ----
#pragma unroll
        for (int kk = 0; kk < 4; kk++) {
            uint32_t a[4][4];
#pragma unroll
            for (int mt = 0; mt < 4; mt++) {
                uint32_t addr = abase + swz((a_row + mt * 16) * 128 + kk * 32 + a_koff);
                ldm_x4(a[mt][0], a[mt][1], a[mt][2], a[mt][3], addr);
            }
            uint32_t b[4][2];
#pragma unroll
            for (int np = 0; np < 2; np++) {
                uint32_t r0, r1, r2, r3;
                uint32_t addr = bbase + swz((b_row + np * 16) * 128 + kk * 32 + b_koff);
                ldm_x4(r0, r1, r2, r3, addr);
                b[np * 2][0] = r0;     b[np * 2][1] = r1;
                b[np * 2 + 1][0] = r2; b[np * 2 + 1][1] = r3;
            }
#pragma unroll
            for (int mt = 0; mt < 4; mt++)
#pragma unroll
                for (int nt = 0; nt < 4; nt++)
                    mma_fp8(acc[mt][nt], a[mt], b[nt][0], b[nt][1]);
        }
        stage = (stage + 1 >= NSTAGE) ? 0 : stage + 1;
    }
    __syncthreads();

    // ---- fused epilogue from accumulator registers (rescale by 1/256) ----
    // c-frag: d0=(r,c0) d1=(r,c0+1) d2=(r+8,c0) d3=(r+8,c0+1); r=lid>>2, c0=2*(lid&3)
#pragma unroll
    for (int mt = 0; mt < 4; mt++) {
#pragma unroll
        for (int h = 0; h < 2; h++) {
            int rloc = wm * 64 + mt * 16 + (lid >> 2) + h * 8;
            int tg = s_tg[rloc];
            float s = 0.0f;
#pragma unroll
            for (int nt = 0; nt < 4; nt++) {
#pragma unroll
                for (int j = 0; j < 2; j++) {
                    int c = cbase + wn * 32 + nt * 8 + 2 * (lid & 3) + j;
                    float v = acc[mt][nt][h * 2 + j] * INV_QQ;
                    if (c < NCLS) {
                        if (c == tg) g_tgt[rbase + rloc] = v;
                        else         s += __expf(S_SCALE * v);
                    }
                }
            }
            // quad reduce (lanes 4t..4t+3 share rloc)
            s += __shfl_xor_sync(0xFFFFFFFFu, s, 1);
            s += __shfl_xor_sync(0xFFFFFFFFu, s, 2);
            if ((lid & 3) == 0) atomicAdd(&s_excl[rloc], s);
        }
    }
    __syncthreads();
    if (tid < BM) atomicAdd(&g_excl[rbase + tid], s_excl[tid]);
}

// ---------------- kernel 4: parallel final reduction ----------------
__global__ void finalize_part_kernel() {
    __shared__ float red[16];
    int tid = threadIdx.x;
    int i = blockIdx.x * 512 + tid;
    float t = g_tgt[i];
    t = fminf(fmaxf(t, -1.0f + 1e-7f), 1.0f - 1e-7f);
    float num = S_SCALE * (t * MARGIN_COS - sqrtf(fmaxf(1.0f - t * t, 0.0f)) * MARGIN_SIN);
    float den = expf(num) + g_excl[i];
    float s = num - logf(den);
#pragma unroll
    for (int o = 16; o; o >>= 1) s += __shfl_xor_sync(0xFFFFFFFFu, s, o);
    if ((tid & 31) == 0) red[tid >> 5] = s;
    __syncthreads();
    if (tid < 16) {
        float v = red[tid];
#pragma unroll
        for (int o = 8; o; o >>= 1) v += __shfl_xor_sync(0xFFFFu, v, o);
        if (tid == 0) atomicAdd(&g_sum, v);
    }
}

__global__ void write_out_kernel(float* __restrict__ out) {
    out[0] = -g_sum / (float)N_ROWS;
}

// ---------------- launch ----------------
extern "C" void kernel_launch(void* const* d_in, const int* in_sizes, int n_in,
                              void* d_out, int out_size) {
    const float* x      = (const float*)d_in[0];
    const float* W      = (const float*)d_in[1];
    const int*   target = (const int*)d_in[2];
    float*       out    = (float*)d_out;

    cudaFuncSetAttribute(arc_gemm_kernel,
                         cudaFuncAttributeMaxDynamicSharedMemorySize, SMEM_TOTAL);

    zero_sum_kernel<<<1, 1>>>();
    conv_w_kernel<<<(int)(((size_t)NCLS * DIM) / 1024), 256>>>(W);
    prep_x_kernel<<<N_ROWS / 8, 256>>>(x);
    arc_gemm_kernel<<<dim3(MTILES, NTILES), 256, SMEM_TOTAL>>>(target);
    finalize_part_kernel<<<N_ROWS / 512, 512>>>();
    write_out_kernel<<<1, 1>>>(out);
}

// round 8
// speedup vs baseline: 1.1581x; 1.1581x over previous
#include <cuda_runtime.h>
#include <cuda_bf16.h>
#include <cstdint>
#include <cstddef>

#define DEV_INLINE __device__ __forceinline__

// ---------------- problem constants (fixed shapes) ----------------
constexpr int N_ROWS = 4096;
constexpr int DIM    = 512;
constexpr int NCLS   = 50000;
constexpr float S_SCALE    = 30.0f;
constexpr float MARGIN_COS = 0.9210609940028851f;  // cos(0.4)
constexpr float MARGIN_SIN = 0.3894183423086505f;  // sin(0.4)

// ---------------- GEMM tiling ----------------
constexpr int BM = 128;
constexpr int BN = 128;
constexpr int BK = 64;                 // 64 bf16 = 128B rows (SW128 atom)
constexpr int NKI = DIM / BK;          // 8 k-iterations
constexpr int NSTAGE = 3;
constexpr int MTILES = N_ROWS / BM;                  // 32
constexpr int NTILES = (NCLS + BN - 1) / BN;         // 391 (last masked)

constexpr uint32_t A_STAGE = BM * 128;               // 16384
constexpr uint32_t B_STAGE = BN * 128;               // 16384
constexpr uint32_t STAGE_BYTES = A_STAGE + B_STAGE;  // 32768
constexpr uint32_t SMEM_EXCL = NSTAGE * STAGE_BYTES;         // 98304
constexpr uint32_t SMEM_TG   = SMEM_EXCL + BM * 4;           // 98816
constexpr uint32_t SMEM_TOTAL = SMEM_TG + BM * 4;            // 99328 (x2 CTA = 199KB)

// ---------------- device scratch (allocation-free rule) ----------------
__device__ __nv_bfloat16 g_xbf[(size_t)N_ROWS * DIM];   // normalized x, bf16
__device__ __nv_bfloat16 g_wbf[(size_t)NCLS * DIM];     // W, bf16 (51MB, mostly L2)
__device__ float g_excl[N_ROWS];
__device__ float g_tgt[N_ROWS];
__device__ float g_sum;

// ---------------- helpers ----------------
DEV_INLINE uint32_t smem_u32(const void* p) { return (uint32_t)__cvta_generic_to_shared(p); }
DEV_INLINE uint32_t swz(uint32_t o) { return o ^ ((o >> 3) & 0x70); }

DEV_INLINE void cp16(uint32_t dst, const void* src) {
    asm volatile("cp.async.cg.shared.global [%0], [%1], 16;" :: "r"(dst), "l"(src));
}

DEV_INLINE void ldm_x4(uint32_t& r0, uint32_t& r1, uint32_t& r2, uint32_t& r3,
                       uint32_t addr) {
    asm volatile("ldmatrix.sync.aligned.m8n8.x4.shared.b16 {%0,%1,%2,%3}, [%4];"
                 : "=r"(r0), "=r"(r1), "=r"(r2), "=r"(r3) : "r"(addr));
}

DEV_INLINE void mma_bf16(float* d, const uint32_t* a, uint32_t b0, uint32_t b1) {
    asm volatile(
        "mma.sync.aligned.m16n8k16.row.col.f32.bf16.bf16.f32 "
        "{%0,%1,%2,%3}, {%4,%5,%6,%7}, {%8,%9}, {%0,%1,%2,%3};"
        : "+f"(d[0]), "+f"(d[1]), "+f"(d[2]), "+f"(d[3])
        : "r"(a[0]), "r"(a[1]), "r"(a[2]), "r"(a[3]), "r"(b0), "r"(b1));
}

// ---------------- kernel 0: zero the loss accumulator ----------------
__global__ void zero_sum_kernel() { g_sum = 0.0f; }

// ---------------- kernel 1: W fp32 -> bf16 ----------------
__global__ void conv_w_kernel(const float* __restrict__ W) {
    size_t i = ((size_t)blockIdx.x * blockDim.x + threadIdx.x) * 4;
    float4 v = *reinterpret_cast<const float4*>(W + i);
    *reinterpret_cast<__nv_bfloat162*>(g_wbf + i)     = __floats2bfloat162_rn(v.x, v.y);
    *reinterpret_cast<__nv_bfloat162*>(g_wbf + i + 2) = __floats2bfloat162_rn(v.z, v.w);
}

// ---------------- kernel 2: normalize x rows -> bf16 (+ zero excl) ----------------
__global__ void prep_x_kernel(const float* __restrict__ x) {
    int row = blockIdx.x * 8 + (threadIdx.x >> 5);
    int lid = threadIdx.x & 31;
    const float* xr = x + (size_t)row * DIM;
    float s = 0.0f;
#pragma unroll
    for (int j = 0; j < 16; j++) { float v = xr[lid + j * 32]; s += v * v; }
#pragma unroll
    for (int o = 16; o; o >>= 1) s += __shfl_xor_sync(0xFFFFFFFFu, s, o);
    float rn = rsqrtf(s);
    __nv_bfloat16* outr = g_xbf + (size_t)row * DIM;
#pragma unroll
    for (int j = 0; j < 16; j++) {
        int d = lid + j * 32;
        outr[d] = __float2bfloat16(xr[d] * rn);
    }
    if (lid == 0) g_excl[row] = 0.0f;   // re-zero on every graph replay
}

// ---------------- kernel 3: HMMA GEMM + fused arcface epilogue ----------------
// BM=128 x BN=128, 8 warps 2x4, 64x32 warp tiles, 2 CTAs/SM, 3-stage cp.async,
// register double-buffered ldmatrix fragments across kk.
__global__ void __launch_bounds__(256, 2)
arc_gemm_kernel(const int* __restrict__ target) {
    extern __shared__ char smem[];
    const uint32_t sb = smem_u32(smem);
    float* s_excl = reinterpret_cast<float*>(smem + SMEM_EXCL);
    int*   s_tg   = reinterpret_cast<int*>(smem + SMEM_TG);

    const int tid = threadIdx.x;
    const int lid = tid & 31;
    const int wid = tid >> 5;
    const int wm  = wid & 1;          // 0..1  (m, 64 rows each)
    const int wn  = wid >> 1;         // 0..3  (n, 32 cols each)
    const int rbase = blockIdx.x * BM;
    const int cbase = blockIdx.y * BN;

    if (tid < BM) {
        s_excl[tid] = 0.0f;
        s_tg[tid]   = target[rbase + tid];
    }

    // cp.async chunking: 16B chunks; row = chunk>>3 (+32 per i), kb = chunk&7
    const int c_row = tid >> 3;
    const int c_kb  = tid & 7;

    // ldmatrix address components (within-stage byte offsets; swizzled at use)
    const uint32_t a_row  = wm * 64 + (lid & 15);
    const uint32_t a_koff = (lid >> 4) * 16;
    const uint32_t b_row  = wn * 32 + (lid & 7) + ((lid >> 4) & 1) * 8;
    const uint32_t b_koff = ((lid >> 3) & 1) * 16;

    float acc[4][4][4];
#pragma unroll
    for (int mt = 0; mt < 4; mt++)
#pragma unroll
        for (int nt = 0; nt < 4; nt++)
#pragma unroll
            for (int j = 0; j < 4; j++) acc[mt][nt][j] = 0.0f;

    // ---- prefetch stages 0 and 1 ----
#pragma unroll
    for (int pk = 0; pk < 2; pk++) {
        const int k0 = pk * BK;
        const uint32_t sa  = sb + pk * STAGE_BYTES;
        const uint32_t sbb = sa + A_STAGE;
        const __nv_bfloat16* xs = g_xbf + (size_t)rbase * DIM + k0;
#pragma unroll
        for (int i = 0; i < 4; i++) {
            int row = c_row + i * 32;
            cp16(sa + swz(row * 128 + c_kb * 16), xs + (size_t)row * DIM + c_kb * 8);
        }
        const __nv_bfloat16* ws = g_wbf + k0;
#pragma unroll
        for (int i = 0; i < 4; i++) {
            int row = c_row + i * 32;
            int c = cbase + row; c = (c < NCLS) ? c : (NCLS - 1);
            cp16(sbb + swz(row * 128 + c_kb * 16), ws + (size_t)c * DIM + c_kb * 8);
        }
        asm volatile("cp.async.commit_group;" ::: "memory");
    }

    // fragment double buffers
    uint32_t afr[2][4][4];
    uint32_t bfr[2][4][2];

    int stage = 0;
    for (int k = 0; k < NKI; k++) {
        if (k == NKI - 1)
            asm volatile("cp.async.wait_group 0;" ::: "memory");
        else
            asm volatile("cp.async.wait_group 1;" ::: "memory");
        __syncthreads();

        const uint32_t abase = sb + stage * STAGE_BYTES;
        const uint32_t bbase = abase + A_STAGE;

        // ---- issue kk=0 fragment loads first (crossbar starts immediately) ----
#pragma unroll
        for (int mt = 0; mt < 4; mt++) {
            uint32_t addr = abase + swz((a_row + mt * 16) * 128 + a_koff);
            ldm_x4(afr[0][mt][0], afr[0][mt][1], afr[0][mt][2], afr[0][mt][3], addr);
        }
#pragma unroll
        for (int np = 0; np < 2; np++) {
            uint32_t r0, r1, r2, r3;
            uint32_t addr = bbase + swz((b_row + np * 16) * 128 + b_koff);
            ldm_x4(r0, r1, r2, r3, addr);
            bfr[0][np * 2][0] = r0;     bfr[0][np * 2][1] = r1;
            bfr[0][np * 2 + 1][0] = r2; bfr[0][np * 2 + 1][1] = r3;
        }

        // ---- then queue cp.async prefetch for stage k+2 ----
        if (k + 2 < NKI) {
            const int ps = (stage + 2 >= NSTAGE) ? stage + 2 - NSTAGE : stage + 2;
            const int k0 = (k + 2) * BK;
            const uint32_t sa  = sb + ps * STAGE_BYTES;
            const uint32_t sbb = sa + A_STAGE;
            const __nv_bfloat16* xs = g_xbf + (size_t)rbase * DIM + k0;
#pragma unroll
            for (int i = 0; i < 4; i++) {
                int row = c_row + i * 32;
                cp16(sa + swz(row * 128 + c_kb * 16), xs + (size_t)row * DIM + c_kb * 8);
            }
            const __nv_bfloat16* ws = g_wbf + k0;
#pragma unroll
            for (int i = 0; i < 4; i++) {
                int row = c_row + i * 32;
                int c = cbase + row; c = (c < NCLS) ? c : (NCLS - 1);
                cp16(sbb + swz(row * 128 + c_kb * 16), ws + (size_t)c * DIM + c_kb * 8);
            }
            asm volatile("cp.async.commit_group;" ::: "memory");
        }

        // ---- pipelined compute: prefetch kk+1 frags, then MMA kk ----
#pragma unroll
        for (int kk = 0; kk < 4; kk++) {
            const int cur = kk & 1, nxt = cur ^ 1;
            if (kk < 3) {
#pragma unroll
                for (int mt = 0; mt < 4; mt++) {
                    uint32_t addr = abase +
                        swz((a_row + mt * 16) * 128 + (kk + 1) * 32 + a_koff);
                    ldm_x4(afr[nxt][mt][0], afr[nxt][mt][1],
                           afr[nxt][mt][2], afr[nxt][mt][3], addr);
                }
#pragma unroll
                for (int np = 0; np < 2; np++) {
                    uint32_t r0, r1, r2, r3;
                    uint32_t addr = bbase +
                        swz((b_row + np * 16) * 128 + (kk + 1) * 32 + b_koff);
                    ldm_x4(r0, r1, r2, r3, addr);
                    bfr[nxt][np * 2][0] = r0;     bfr[nxt][np * 2][1] = r1;
                    bfr[nxt][np * 2 + 1][0] = r2; bfr[nxt][np * 2 + 1][1] = r3;
                }
            }
#pragma unroll
            for (int mt = 0; mt < 4; mt++)
#pragma unroll
                for (int nt = 0; nt < 4; nt++)
                    mma_bf16(acc[mt][nt], afr[cur][mt], bfr[cur][nt][0], bfr[cur][nt][1]);
        }
        stage = (stage + 1 >= NSTAGE) ? 0 : stage + 1;
    }
    // no barrier needed here: s_tg/s_excl init ordered by loop barriers,
    // epilogue reads only per-thread registers + does atomics.

    // ---- fused epilogue from accumulator registers ----
    // c-frag: d0=(r,c0) d1=(r,c0+1) d2=(r+8,c0) d3=(r+8,c0+1); r=lid>>2, c0=2*(lid&3)
#pragma unroll
    for (int mt = 0; mt < 4; mt++) {
#pragma unroll
        for (int h = 0; h < 2; h++) {
            int rloc = wm * 64 + mt * 16 + (lid >> 2) + h * 8;
            int tg = s_tg[rloc];
            float s = 0.0f;
#pragma unroll
            for (int nt = 0; nt < 4; nt++) {
#pragma unroll
                for (int j = 0; j < 2; j++) {
                    int c = cbase + wn * 32 + nt * 8 + 2 * (lid & 3) + j;
                    float v = acc[mt][nt][h * 2 + j];
                    if (c < NCLS) {
                        if (c == tg) g_tgt[rbase + rloc] = v;
                        else         s += __expf(S_SCALE * v);
                    }
                }
            }
            // quad reduce (lanes 4t..4t+3 share rloc)
            s += __shfl_xor_sync(0xFFFFFFFFu, s, 1);
            s += __shfl_xor_sync(0xFFFFFFFFu, s, 2);
            if ((lid & 3) == 0) atomicAdd(&s_excl[rloc], s);
        }
    }
    __syncthreads();
    if (tid < BM) atomicAdd(&g_excl[rbase + tid], s_excl[tid]);
}

// ---------------- kernel 4: parallel final reduction ----------------
__global__ void finalize_part_kernel() {
    __shared__ float red[16];
    int tid = threadIdx.x;
    int i = blockIdx.x * 512 + tid;
    float t = g_tgt[i];
    t = fminf(fmaxf(t, -1.0f + 1e-7f), 1.0f - 1e-7f);
    float num = S_SCALE * (t * MARGIN_COS - sqrtf(fmaxf(1.0f - t * t, 0.0f)) * MARGIN_SIN);
    float den = expf(num) + g_excl[i];
    float s = num - logf(den);
#pragma unroll
    for (int o = 16; o; o >>= 1) s += __shfl_xor_sync(0xFFFFFFFFu, s, o);
    if ((tid & 31) == 0) red[tid >> 5] = s;
    __syncthreads();
    if (tid < 16) {
        float v = red[tid];
#pragma unroll
        for (int o = 8; o; o >>= 1) v += __shfl_xor_sync(0xFFFFu, v, o);
        if (tid == 0) atomicAdd(&g_sum, v);
    }
}

__global__ void write_out_kernel(float* __restrict__ out) {
    out[0] = -g_sum / (float)N_ROWS;
}

// ---------------- launch ----------------
extern "C" void kernel_launch(void* const* d_in, const int* in_sizes, int n_in,
                              void* d_out, int out_size) {
    const float* x      = (const float*)d_in[0];
    const float* W      = (const float*)d_in[1];
    const int*   target = (const int*)d_in[2];
    float*       out    = (float*)d_out;

    cudaFuncSetAttribute(arc_gemm_kernel,
                         cudaFuncAttributeMaxDynamicSharedMemorySize, SMEM_TOTAL);

    zero_sum_kernel<<<1, 1>>>();
    conv_w_kernel<<<(int)(((size_t)NCLS * DIM) / 1024), 256>>>(W);
    prep_x_kernel<<<N_ROWS / 8, 256>>>(x);
    arc_gemm_kernel<<<dim3(MTILES, NTILES), 256, SMEM_TOTAL>>>(target);
    finalize_part_kernel<<<N_ROWS / 512, 512>>>();
    write_out_kernel<<<1, 1>>>(out);
}

// round 9
// speedup vs baseline: 1.1946x; 1.0315x over previous
#include <cuda_runtime.h>
#include <cuda_bf16.h>
#include <cstdint>
#include <cstddef>

#define DEV_INLINE __device__ __forceinline__

// ---------------- problem constants (fixed shapes) ----------------
constexpr int N_ROWS = 4096;
constexpr int DIM    = 512;
constexpr int NCLS   = 50000;
constexpr float S_SCALE    = 30.0f;
constexpr float MARGIN_COS = 0.9210609940028851f;  // cos(0.4)
constexpr float MARGIN_SIN = 0.3894183423086505f;  // sin(0.4)

// ---------------- GEMM tiling ----------------
constexpr int BM = 128;
constexpr int BN = 128;
constexpr int BK = 64;                 // 64 bf16 = 128B rows (SW128 atom)
constexpr int NKI = DIM / BK;          // 8 k-iterations
constexpr int NSTAGE = 3;
constexpr int MTILES = N_ROWS / BM;                  // 32
constexpr int NTILES = (NCLS + BN - 1) / BN;         // 391 (last masked)

constexpr uint32_t A_STAGE = BM * 128;               // 16384
constexpr uint32_t B_STAGE = BN * 128;               // 16384
constexpr uint32_t STAGE_BYTES = A_STAGE + B_STAGE;  // 32768
constexpr uint32_t SMEM_EXCL = NSTAGE * STAGE_BYTES;         // 98304
constexpr uint32_t SMEM_TG   = SMEM_EXCL + BM * 4;           // 98816
constexpr uint32_t SMEM_TOTAL = SMEM_TG + BM * 4;            // 99328 (x2 CTA = 199KB)

// ---------------- device scratch (allocation-free rule) ----------------
__device__ __nv_bfloat16 g_xbf[(size_t)N_ROWS * DIM];   // normalized x, bf16
__device__ __nv_bfloat16 g_wbf[(size_t)NCLS * DIM];     // W, bf16 (51MB, mostly L2)
__device__ float g_excl[N_ROWS];
__device__ float g_tgt[N_ROWS];
__device__ float g_sum;

// ---------------- helpers ----------------
DEV_INLINE uint32_t smem_u32(const void* p) { return (uint32_t)__cvta_generic_to_shared(p); }
DEV_INLINE uint32_t swz(uint32_t o) { return o ^ ((o >> 3) & 0x70); }

DEV_INLINE void cp16(uint32_t dst, const void* src) {
    asm volatile("cp.async.cg.shared.global [%0], [%1], 16;" :: "r"(dst), "l"(src));
}

DEV_INLINE void ldm_x4(uint32_t& r0, uint32_t& r1, uint32_t& r2, uint32_t& r3,
                       uint32_t addr) {
    asm volatile("ldmatrix.sync.aligned.m8n8.x4.shared.b16 {%0,%1,%2,%3}, [%4];"
                 : "=r"(r0), "=r"(r1), "=r"(r2), "=r"(r3) : "r"(addr));
}

DEV_INLINE void mma_bf16(float* d, const uint32_t* a, uint32_t b0, uint32_t b1) {
    asm volatile(
        "mma.sync.aligned.m16n8k16.row.col.f32.bf16.bf16.f32 "
        "{%0,%1,%2,%3}, {%4,%5,%6,%7}, {%8,%9}, {%0,%1,%2,%3};"
        : "+f"(d[0]), "+f"(d[1]), "+f"(d[2]), "+f"(d[3])
        : "r"(a[0]), "r"(a[1]), "r"(a[2]), "r"(a[3]), "r"(b0), "r"(b1));
}

// ---------------- kernel 1: W fp32 -> bf16 (+ zero g_sum) ----------------
__global__ void conv_w_kernel(const float* __restrict__ W) {
    if (blockIdx.x == 0 && threadIdx.x == 0) g_sum = 0.0f;
    size_t i = ((size_t)blockIdx.x * blockDim.x + threadIdx.x) * 4;
    float4 v = *reinterpret_cast<const float4*>(W + i);
    *reinterpret_cast<__nv_bfloat162*>(g_wbf + i)     = __floats2bfloat162_rn(v.x, v.y);
    *reinterpret_cast<__nv_bfloat162*>(g_wbf + i + 2) = __floats2bfloat162_rn(v.z, v.w);
}

// ---------------- kernel 2: normalize x rows -> bf16 (+ zero excl) ----------------
__global__ void prep_x_kernel(const float* __restrict__ x) {
    int row = blockIdx.x * 8 + (threadIdx.x >> 5);
    int lid = threadIdx.x & 31;
    const float* xr = x + (size_t)row * DIM;
    float s = 0.0f;
#pragma unroll
    for (int j = 0; j < 16; j++) { float v = xr[lid + j * 32]; s += v * v; }
#pragma unroll
    for (int o = 16; o; o >>= 1) s += __shfl_xor_sync(0xFFFFFFFFu, s, o);
    float rn = rsqrtf(s);
    __nv_bfloat16* outr = g_xbf + (size_t)row * DIM;
#pragma unroll
    for (int j = 0; j < 16; j++) {
        int d = lid + j * 32;
        outr[d] = __float2bfloat16(xr[d] * rn);
    }
    if (lid == 0) g_excl[row] = 0.0f;   // re-zero on every graph replay
}

// ---------------- kernel 3: HMMA GEMM + fused arcface epilogue ----------------
// BM=128 x BN=128, 8 warps 2x4, 64x32 warp tiles, 2 CTAs/SM, 3-stage cp.async.
// Precomputed incremental smem addresses; kk=0 LDSM issued before prefetch.
__global__ void __launch_bounds__(256, 2)
arc_gemm_kernel(const int* __restrict__ target) {
    extern __shared__ char smem[];
    const uint32_t sb = smem_u32(smem);
    float* s_excl = reinterpret_cast<float*>(smem + SMEM_EXCL);
    int*   s_tg   = reinterpret_cast<int*>(smem + SMEM_TG);

    const int tid = threadIdx.x;
    const int lid = tid & 31;
    const int wid = tid >> 5;
    const int wm  = wid & 1;          // 0..1  (m, 64 rows each)
    const int wn  = wid >> 1;         // 0..3  (n, 32 cols each)
    const int rbase = blockIdx.x * BM;
    const int cbase = blockIdx.y * BN;

    if (tid < BM) {
        s_excl[tid] = 0.0f;
        s_tg[tid]   = target[rbase + tid];
    }

    // ---- cp.async source pointers & dst offsets, hoisted out of the k-loop ----
    const int c_row = tid >> 3;          // rows advance by 32 per i
    const int c_kb  = tid & 7;
    const __nv_bfloat16* xp[4];
    const __nv_bfloat16* wp[4];
    uint32_t dstoff[4];
#pragma unroll
    for (int i = 0; i < 4; i++) {
        int row = c_row + i * 32;
        xp[i] = g_xbf + (size_t)(rbase + row) * DIM + c_kb * 8;
        int c = cbase + row; c = (c < NCLS) ? c : (NCLS - 1);  // clamp hoisted
        wp[i] = g_wbf + (size_t)c * DIM + c_kb * 8;
        dstoff[i] = swz(row * 128 + c_kb * 16);
    }

    // ---- LDSM address decomposition: addr = base + rowoff[.] + xk[kk] ----
    // swz(row*128 + off) = row*128 + (off ^ ((row&7)<<4)) for off<128,
    // and (row + 16*mt)&7 == row&7, so one mask per operand suffices.
    const uint32_t a_row  = wm * 64 + (lid & 15);
    const uint32_t a_koff = (lid >> 4) * 16;
    const uint32_t b_row  = wn * 32 + (lid & 7) + ((lid >> 4) & 1) * 8;
    const uint32_t b_koff = ((lid >> 3) & 1) * 16;
    const uint32_t maskA  = (a_row & 7) << 4;
    const uint32_t maskB  = (b_row & 7) << 4;
    uint32_t offA[4], offB[2], xka[4], xkb[4];
#pragma unroll
    for (int mt = 0; mt < 4; mt++) offA[mt] = (a_row + mt * 16) * 128;
#pragma unroll
    for (int np = 0; np < 2; np++) offB[np] = (b_row + np * 16) * 128;
#pragma unroll
    for (int kk = 0; kk < 4; kk++) {
        xka[kk] = (kk * 32 + a_koff) ^ maskA;
        xkb[kk] = (kk * 32 + b_koff) ^ maskB;
    }

    float acc[4][4][4];
#pragma unroll
    for (int mt = 0; mt < 4; mt++)
#pragma unroll
        for (int nt = 0; nt < 4; nt++)
#pragma unroll
            for (int j = 0; j < 4; j++) acc[mt][nt][j] = 0.0f;

    // ---- prefetch stages 0 and 1 ----
#pragma unroll
    for (int pk = 0; pk < 2; pk++) {
        const int k0 = pk * BK;
        const uint32_t sa  = sb + pk * STAGE_BYTES;
        const uint32_t sbb = sa + A_STAGE;
#pragma unroll
        for (int i = 0; i < 4; i++) cp16(sa + dstoff[i], xp[i] + k0);
#pragma unroll
        for (int i = 0; i < 4; i++) cp16(sbb + dstoff[i], wp[i] + k0);
        asm volatile("cp.async.commit_group;" ::: "memory");
    }

    uint32_t afr[4][4];
    uint32_t bfr[4][2];

    int stage = 0;
    for (int k = 0; k < NKI; k++) {
        if (k == NKI - 1)
            asm volatile("cp.async.wait_group 0;" ::: "memory");
        else
            asm volatile("cp.async.wait_group 1;" ::: "memory");
        __syncthreads();

        const uint32_t abase = sb + stage * STAGE_BYTES;
        const uint32_t bbase = abase + A_STAGE;

        // ---- kk=0 fragment loads first: crossbar starts immediately ----
        {
            const uint32_t ax = abase + xka[0];
            const uint32_t bx = bbase + xkb[0];
#pragma unroll
            for (int mt = 0; mt < 4; mt++)
                ldm_x4(afr[mt][0], afr[mt][1], afr[mt][2], afr[mt][3], ax + offA[mt]);
#pragma unroll
            for (int np = 0; np < 2; np++) {
                uint32_t r0, r1, r2, r3;
                ldm_x4(r0, r1, r2, r3, bx + offB[np]);
                bfr[np * 2][0] = r0;     bfr[np * 2][1] = r1;
                bfr[np * 2 + 1][0] = r2; bfr[np * 2 + 1][1] = r3;
            }
        }

        // ---- queue cp.async prefetch for stage k+2 (overlaps LDSM latency) ----
        if (k + 2 < NKI) {
            const int ps = (stage + 2 >= NSTAGE) ? stage + 2 - NSTAGE : stage + 2;
            const int k0 = (k + 2) * BK;
            const uint32_t sa  = sb + ps * STAGE_BYTES;
            const uint32_t sbb = sa + A_STAGE;
#pragma unroll
            for (int i = 0; i < 4; i++) cp16(sa + dstoff[i], xp[i] + k0);
#pragma unroll
            for (int i = 0; i < 4; i++) cp16(sbb + dstoff[i], wp[i] + k0);
            asm volatile("cp.async.commit_group;" ::: "memory");
        }

        // ---- kk loop: MMA(kk), then LDSM(kk+1) into the same registers ----
#pragma unroll
        for (int kk = 0; kk < 4; kk++) {
#pragma unroll
            for (int mt = 0; mt < 4; mt++)
#pragma unroll
                for (int nt = 0; nt < 4; nt++)
                    mma_bf16(acc[mt][nt], afr[mt], bfr[nt][0], bfr[nt][1]);
            if (kk < 3) {
                const uint32_t ax = abase + xka[kk + 1];
                const uint32_t bx = bbase + xkb[kk + 1];
#pragma unroll
                for (int mt = 0; mt < 4; mt++)
                    ldm_x4(afr[mt][0], afr[mt][1], afr[mt][2], afr[mt][3],
                           ax + offA[mt]);
#pragma unroll
                for (int np = 0; np < 2; np++) {
                    uint32_t r0, r1, r2, r3;
                    ldm_x4(r0, r1, r2, r3, bx + offB[np]);
                    bfr[np * 2][0] = r0;     bfr[np * 2][1] = r1;
                    bfr[np * 2 + 1][0] = r2; bfr[np * 2 + 1][1] = r3;
                }
            }
        }
        stage = (stage + 1 >= NSTAGE) ? 0 : stage + 1;
    }
    // epilogue reads only registers + atomics; s_tg ordered by loop barriers.

    // ---- fused epilogue from accumulator registers ----
    // c-frag: d0=(r,c0) d1=(r,c0+1) d2=(r+8,c0) d3=(r+8,c0+1); r=lid>>2, c0=2*(lid&3)
#pragma unroll
    for (int mt = 0; mt < 4; mt++) {
#pragma unroll
        for (int h = 0; h < 2; h++) {
            int rloc = wm * 64 + mt * 16 + (lid >> 2) + h * 8;
            int tg = s_tg[rloc];
            float s = 0.0f;
#pragma unroll
            for (int nt = 0; nt < 4; nt++) {
#pragma unroll
                for (int j = 0; j < 2; j++) {
                    int c = cbase + wn * 32 + nt * 8 + 2 * (lid & 3) + j;
                    float v = acc[mt][nt][h * 2 + j];
                    if (c < NCLS) {
                        if (c == tg) g_tgt[rbase + rloc] = v;
                        else         s += __expf(S_SCALE * v);
                    }
                }
            }
            // quad reduce (lanes 4t..4t+3 share rloc)
            s += __shfl_xor_sync(0xFFFFFFFFu, s, 1);
            s += __shfl_xor_sync(0xFFFFFFFFu, s, 2);
            if ((lid & 3) == 0) atomicAdd(&s_excl[rloc], s);
        }
    }
    __syncthreads();
    if (tid < BM) atomicAdd(&g_excl[rbase + tid], s_excl[tid]);
}

// ---------------- kernel 4: parallel final reduction ----------------
__global__ void finalize_part_kernel() {
    __shared__ float red[16];
    int tid = threadIdx.x;
    int i = blockIdx.x * 512 + tid;
    float t = g_tgt[i];
    t = fminf(fmaxf(t, -1.0f + 1e-7f), 1.0f - 1e-7f);
    float num = S_SCALE * (t * MARGIN_COS - sqrtf(fmaxf(1.0f - t * t, 0.0f)) * MARGIN_SIN);
    float den = expf(num) + g_excl[i];
    float s = num - logf(den);
#pragma unroll
    for (int o = 16; o; o >>= 1) s += __shfl_xor_sync(0xFFFFFFFFu, s, o);
    if ((tid & 31) == 0) red[tid >> 5] = s;
    __syncthreads();
    if (tid < 16) {
        float v = red[tid];
#pragma unroll
        for (int o = 8; o; o >>= 1) v += __shfl_xor_sync(0xFFFFu, v, o);
        if (tid == 0) atomicAdd(&g_sum, v);
    }
}

__global__ void write_out_kernel(float* __restrict__ out) {
    out[0] = -g_sum / (float)N_ROWS;
}

// ---------------- launch ----------------
extern "C" void kernel_launch(void* const* d_in, const int* in_sizes, int n_in,
                              void* d_out, int out_size) {
    const float* x      = (const float*)d_in[0];
    const float* W      = (const float*)d_in[1];
    const int*   target = (const int*)d_in[2];
    float*       out    = (float*)d_out;

    cudaFuncSetAttribute(arc_gemm_kernel,
                         cudaFuncAttributeMaxDynamicSharedMemorySize, SMEM_TOTAL);

    conv_w_kernel<<<(int)(((size_t)NCLS * DIM) / 1024), 256>>>(W);
    prep_x_kernel<<<N_ROWS / 8, 256>>>(x);
    arc_gemm_kernel<<<dim3(MTILES, NTILES), 256, SMEM_TOTAL>>>(target);
    finalize_part_kernel<<<N_ROWS / 512, 512>>>();
    write_out_kernel<<<1, 1>>>(out);
}

// round 10
// speedup vs baseline: 1.3487x; 1.1290x over previous
#include <cuda_runtime.h>
#include <cuda_bf16.h>
#include <cstdint>
#include <cstddef>

#define DEV_INLINE __device__ __forceinline__

// ---------------- problem constants (fixed shapes) ----------------
constexpr int N_ROWS = 4096;
constexpr int DIM    = 512;
constexpr int NCLS   = 50000;
constexpr float S_SCALE    = 30.0f;
constexpr float MARGIN_COS = 0.9210609940028851f;  // cos(0.4)
constexpr float MARGIN_SIN = 0.3894183423086505f;  // sin(0.4)

// ---------------- GEMM tiling ----------------
constexpr int BM = 128;
constexpr int BN = 128;
constexpr int BK = 64;                 // 64 bf16 = 128B rows (SW128 atom)
constexpr int NKI = DIM / BK;          // 8 k-iterations
constexpr int NSTAGE = 3;
constexpr int MTILES = N_ROWS / BM;                  // 32
constexpr int NTILES = (NCLS + BN - 1) / BN;         // 391 (last masked)

constexpr uint32_t A_STAGE = BM * 128;               // 16384
constexpr uint32_t B_STAGE = BN * 128;               // 16384
constexpr uint32_t STAGE_BYTES = A_STAGE + B_STAGE;  // 32768
constexpr uint32_t SMEM_EXCL = NSTAGE * STAGE_BYTES;         // 98304
constexpr uint32_t SMEM_TG   = SMEM_EXCL + BM * 4;           // 98816
constexpr uint32_t SMEM_MBAR = SMEM_TG + BM * 4;             // 99328
constexpr uint32_t SMEM_TOTAL = SMEM_MBAR + NSTAGE * 16;     // 99376 (x2 = 198.8KB)

// mbar layout: full[s] at SMEM_MBAR + s*16, empty[s] at +8
#define FULL_MB(s)  (sb + SMEM_MBAR + (s) * 16)
#define EMPTY_MB(s) (sb + SMEM_MBAR + (s) * 16 + 8)

// ---------------- device scratch (allocation-free rule) ----------------
__device__ __nv_bfloat16 g_xbf[(size_t)N_ROWS * DIM];   // normalized x, bf16
__device__ __nv_bfloat16 g_wbf[(size_t)NCLS * DIM];     // W, bf16 (51MB, mostly L2)
__device__ float g_excl[N_ROWS];
__device__ float g_tgt[N_ROWS];
__device__ float g_sum;

// ---------------- helpers ----------------
DEV_INLINE uint32_t smem_u32(const void* p) { return (uint32_t)__cvta_generic_to_shared(p); }
DEV_INLINE uint32_t swz(uint32_t o) { return o ^ ((o >> 3) & 0x70); }

DEV_INLINE void cp16(uint32_t dst, const void* src) {
    asm volatile("cp.async.cg.shared.global [%0], [%1], 16;" :: "r"(dst), "l"(src));
}

DEV_INLINE void cp_arrive(uint32_t mbar) {
    asm volatile("cp.async.mbarrier.arrive.noinc.shared.b64 [%0];"
                 :: "r"(mbar) : "memory");
}

DEV_INLINE void mbar_arrive(uint32_t mbar) {
    asm volatile("mbarrier.arrive.shared.b64 _, [%0];" :: "r"(mbar) : "memory");
}

DEV_INLINE void mbar_wait(uint32_t mbar, uint32_t parity) {
    asm volatile(
        "{\n\t.reg .pred P1;\n\t"
        "WL_%=:\n\t"
        "mbarrier.try_wait.parity.acquire.cta.shared::cta.b64 P1, [%0], %1, 0x989680;\n\t"
        "@P1 bra.uni WD_%=;\n\t"
        "bra.uni WL_%=;\n\t"
        "WD_%=:\n\t}"
        :: "r"(mbar), "r"(parity) : "memory");
}

DEV_INLINE void ldm_x4(uint32_t& r0, uint32_t& r1, uint32_t& r2, uint32_t& r3,
                       uint32_t addr) {
    asm volatile("ldmatrix.sync.aligned.m8n8.x4.shared.b16 {%0,%1,%2,%3}, [%4];"
                 : "=r"(r0), "=r"(r1), "=r"(r2), "=r"(r3) : "r"(addr));
}

DEV_INLINE void mma_bf16(float* d, const uint32_t* a, uint32_t b0, uint32_t b1) {
    asm volatile(
        "mma.sync.aligned.m16n8k16.row.col.f32.bf16.bf16.f32 "
        "{%0,%1,%2,%3}, {%4,%5,%6,%7}, {%8,%9}, {%0,%1,%2,%3};"
        : "+f"(d[0]), "+f"(d[1]), "+f"(d[2]), "+f"(d[3])
        : "r"(a[0]), "r"(a[1]), "r"(a[2]), "r"(a[3]), "r"(b0), "r"(b1));
}

// ---------------- kernel 1: W fp32 -> bf16 (+ zero g_sum) ----------------
__global__ void conv_w_kernel(const float* __restrict__ W) {
    if (blockIdx.x == 0 && threadIdx.x == 0) g_sum = 0.0f;
    size_t i = ((size_t)blockIdx.x * blockDim.x + threadIdx.x) * 4;
    float4 v = *reinterpret_cast<const float4*>(W + i);
    *reinterpret_cast<__nv_bfloat162*>(g_wbf + i)     = __floats2bfloat162_rn(v.x, v.y);
    *reinterpret_cast<__nv_bfloat162*>(g_wbf + i + 2) = __floats2bfloat162_rn(v.z, v.w);
}

// ---------------- kernel 2: normalize x rows -> bf16 (+ zero excl) ----------------
__global__ void prep_x_kernel(const float* __restrict__ x) {
    int row = blockIdx.x * 8 + (threadIdx.x >> 5);
    int lid = threadIdx.x & 31;
    const float* xr = x + (size_t)row * DIM;
    float s = 0.0f;
#pragma unroll
    for (int j = 0; j < 16; j++) { float v = xr[lid + j * 32]; s += v * v; }
#pragma unroll
    for (int o = 16; o; o >>= 1) s += __shfl_xor_sync(0xFFFFFFFFu, s, o);
    float rn = rsqrtf(s);
    __nv_bfloat16* outr = g_xbf + (size_t)row * DIM;
#pragma unroll
    for (int j = 0; j < 16; j++) {
        int d = lid + j * 32;
        outr[d] = __float2bfloat16(xr[d] * rn);
    }
    if (lid == 0) g_excl[row] = 0.0f;   // re-zero on every graph replay
}

// ---------------- kernel 3: HMMA GEMM + fused arcface epilogue ----------------
// BM=128 x BN=128, 8 warps 2x4, 64x32 warp tiles, 2 CTAs/SM.
// mbarrier producer/consumer pipeline: NO __syncthreads in the mainloop.
__global__ void __launch_bounds__(256, 2)
arc_gemm_kernel(const int* __restrict__ target) {
    extern __shared__ char smem[];
    const uint32_t sb = smem_u32(smem);
    float* s_excl = reinterpret_cast<float*>(smem + SMEM_EXCL);
    int*   s_tg   = reinterpret_cast<int*>(smem + SMEM_TG);

    const int tid = threadIdx.x;
    const int lid = tid & 31;
    const int wid = tid >> 5;
    const int wm  = wid & 1;          // 0..1  (m, 64 rows each)
    const int wn  = wid >> 1;         // 0..3  (n, 32 cols each)
    const int rbase = blockIdx.x * BM;
    const int cbase = blockIdx.y * BN;

    if (tid == 0) {
#pragma unroll
        for (int s = 0; s < NSTAGE; s++) {
            asm volatile("mbarrier.init.shared.b64 [%0], 256;" :: "r"(FULL_MB(s))  : "memory");
            asm volatile("mbarrier.init.shared.b64 [%0], 256;" :: "r"(EMPTY_MB(s)) : "memory");
        }
    }
    if (tid < BM) {
        s_excl[tid] = 0.0f;
        s_tg[tid]   = target[rbase + tid];
    }
    __syncthreads();   // orders mbarrier init + s_tg/s_excl before everything

    // ---- cp.async source pointers & dst offsets, hoisted ----
    const int c_row = tid >> 3;          // rows advance by 32 per i
    const int c_kb  = tid & 7;
    const __nv_bfloat16* xp[4];
    const __nv_bfloat16* wp[4];
    uint32_t dstoff[4];
#pragma unroll
    for (int i = 0; i < 4; i++) {
        int row = c_row + i * 32;
        xp[i] = g_xbf + (size_t)(rbase + row) * DIM + c_kb * 8;
        int c = cbase + row; c = (c < NCLS) ? c : (NCLS - 1);  // clamp hoisted
        wp[i] = g_wbf + (size_t)c * DIM + c_kb * 8;
        dstoff[i] = swz(row * 128 + c_kb * 16);
    }

    // ---- LDSM address decomposition (R8 scheme) ----
    const uint32_t a_row  = wm * 64 + (lid & 15);
    const uint32_t a_koff = (lid >> 4) * 16;
    const uint32_t b_row  = wn * 32 + (lid & 7) + ((lid >> 4) & 1) * 8;
    const uint32_t b_koff = ((lid >> 3) & 1) * 16;
    const uint32_t maskA  = (a_row & 7) << 4;
    const uint32_t maskB  = (b_row & 7) << 4;
    uint32_t offA[4], offB[2], xka[4], xkb[4];
#pragma unroll
    for (int mt = 0; mt < 4; mt++) offA[mt] = (a_row + mt * 16) * 128;
#pragma unroll
    for (int np = 0; np < 2; np++) offB[np] = (b_row + np * 16) * 128;
#pragma unroll
    for (int kk = 0; kk < 4; kk++) {
        xka[kk] = (kk * 32 + a_koff) ^ maskA;
        xkb[kk] = (kk * 32 + b_koff) ^ maskB;
    }

    float acc[4][4][4];
#pragma unroll
    for (int mt = 0; mt < 4; mt++)
#pragma unroll
        for (int nt = 0; nt < 4; nt++)
#pragma unroll
            for (int j = 0; j < 4; j++) acc[mt][nt][j] = 0.0f;

    // ---- prologue: fill stages 0 and 1 (fresh, no empty wait) ----
#pragma unroll
    for (int pk = 0; pk < 2; pk++) {
        const int k0 = pk * BK;
        const uint32_t sa  = sb + pk * STAGE_BYTES;
        const uint32_t sbb = sa + A_STAGE;
#pragma unroll
        for (int i = 0; i < 4; i++) cp16(sa + dstoff[i], xp[i] + k0);
#pragma unroll
        for (int i = 0; i < 4; i++) cp16(sbb + dstoff[i], wp[i] + k0);
        cp_arrive(FULL_MB(pk));
    }

    uint32_t afr[4][4];
    uint32_t bfr[4][2];

    // ---- mainloop: fully unrolled, all stage indices/parities compile-time ----
    // stage s = k%3. full[s] consumed at k with parity (k/3)&1.
    // fills: k+2 for k in [0,5]; fill index fi = (k+2)/3; empty wait parity (fi-1)&1,
    //        skipped for the first fill of stage 2 (k+2 == 2).
#pragma unroll
    for (int k = 0; k < NKI; k++) {
        const int s = k % 3;
        const uint32_t abase = sb + s * STAGE_BYTES;
        const uint32_t bbase = abase + A_STAGE;

        mbar_wait(FULL_MB(s), (k / 3) & 1);

        // kk=0 fragment loads first: crossbar starts immediately
        {
            const uint32_t ax = abase + xka[0];
            const uint32_t bx = bbase + xkb[0];
#pragma unroll
            for (int mt = 0; mt < 4; mt++)
                ldm_x4(afr[mt][0], afr[mt][1], afr[mt][2], afr[mt][3], ax + offA[mt]);
#pragma unroll
            for (int np = 0; np < 2; np++) {
                uint32_t r0, r1, r2, r3;
                ldm_x4(r0, r1, r2, r3, bx + offB[np]);
                bfr[np * 2][0] = r0;     bfr[np * 2][1] = r1;
                bfr[np * 2 + 1][0] = r2; bfr[np * 2 + 1][1] = r3;
            }
        }

        // produce stage k+2
        if (k + 2 < NKI) {
            const int s2 = (k + 2) % 3;
            const int fi = (k + 2) / 3;          // 0 => fresh (stage 2 only)
            if (k + 2 > 2) mbar_wait(EMPTY_MB(s2), (fi - 1) & 1);
            const int k0 = (k + 2) * BK;
            const uint32_t sa  = sb + s2 * STAGE_BYTES;
            const uint32_t sbb = sa + A_STAGE;
#pragma unroll
            for (int i = 0; i < 4; i++) cp16(sa + dstoff[i], xp[i] + k0);
#pragma unroll
            for (int i = 0; i < 4; i++) cp16(sbb + dstoff[i], wp[i] + k0);
            cp_arrive(FULL_MB(s2));
        }

        // kk loop: MMA(kk), then LDSM(kk+1)
#pragma unroll
        for (int kk = 0; kk < 4; kk++) {
#pragma unroll
            for (int mt = 0; mt < 4; mt++)
#pragma unroll
                for (int nt = 0; nt < 4; nt++)
                    mma_bf16(acc[mt][nt], afr[mt], bfr[nt][0], bfr[nt][1]);
            if (kk < 3) {
                const uint32_t ax = abase + xka[kk + 1];
                const uint32_t bx = bbase + xkb[kk + 1];
#pragma unroll
                for (int mt = 0; mt < 4; mt++)
                    ldm_x4(afr[mt][0], afr[mt][1], afr[mt][2], afr[mt][3],
                           ax + offA[mt]);
#pragma unroll
                for (int np = 0; np < 2; np++) {
                    uint32_t r0, r1, r2, r3;
                    ldm_x4(r0, r1, r2, r3, bx + offB[np]);
                    bfr[np * 2][0] = r0;     bfr[np * 2][1] = r1;
                    bfr[np * 2 + 1][0] = r2; bfr[np * 2 + 1][1] = r3;
                }
            }
        }

        // release the stage for refill (only needed while fills remain)
        if (k + 3 < NKI) mbar_arrive(EMPTY_MB(s));
    }

    // ---- fused epilogue from accumulator registers ----
    // c-frag: d0=(r,c0) d1=(r,c0+1) d2=(r+8,c0) d3=(r+8,c0+1); r=lid>>2, c0=2*(lid&3)
#pragma unroll
    for (int mt = 0; mt < 4; mt++) {
#pragma unroll
        for (int h = 0; h < 2; h++) {
            int rloc = wm * 64 + mt * 16 + (lid >> 2) + h * 8;
            int tg = s_tg[rloc];
            float s = 0.0f;
#pragma unroll
            for (int nt = 0; nt < 4; nt++) {
#pragma unroll
                for (int j = 0; j < 2; j++) {
                    int c = cbase + wn * 32 + nt * 8 + 2 * (lid & 3) + j;
                    float v = acc[mt][nt][h * 2 + j];
                    if (c < NCLS) {
                        if (c == tg) g_tgt[rbase + rloc] = v;
                        else         s += __expf(S_SCALE * v);
                    }
                }
            }
            // quad reduce (lanes 4t..4t+3 share rloc)
            s += __shfl_xor_sync(0xFFFFFFFFu, s, 1);
            s += __shfl_xor_sync(0xFFFFFFFFu, s, 2);
            if ((lid & 3) == 0) atomicAdd(&s_excl[rloc], s);
        }
    }
    __syncthreads();
    if (tid < BM) atomicAdd(&g_excl[rbase + tid], s_excl[tid]);
}

// ---------------- kernel 4: parallel final reduction ----------------
__global__ void finalize_part_kernel() {
    __shared__ float red[16];
    int tid = threadIdx.x;
    int i = blockIdx.x * 512 + tid;
    float t = g_tgt[i];
    t = fminf(fmaxf(t, -1.0f + 1e-7f), 1.0f - 1e-7f);
    float num = S_SCALE * (t * MARGIN_COS - sqrtf(fmaxf(1.0f - t * t, 0.0f)) * MARGIN_SIN);
    float den = expf(num) + g_excl[i];
    float s = num - logf(den);
#pragma unroll
    for (int o = 16; o; o >>= 1) s += __shfl_xor_sync(0xFFFFFFFFu, s, o);
    if ((tid & 31) == 0) red[tid >> 5] = s;
    __syncthreads();
    if (tid < 16) {
        float v = red[tid];
#pragma unroll
        for (int o = 8; o; o >>= 1) v += __shfl_xor_sync(0xFFFFu, v, o);
        if (tid == 0) atomicAdd(&g_sum, v);
    }
}

__global__ void write_out_kernel(float* __restrict__ out) {
    out[0] = -g_sum / (float)N_ROWS;
}

// ---------------- launch ----------------
extern "C" void kernel_launch(void* const* d_in, const int* in_sizes, int n_in,
                              void* d_out, int out_size) {
    const float* x      = (const float*)d_in[0];
    const float* W      = (const float*)d_in[1];
    const int*   target = (const int*)d_in[2];
    float*       out    = (float*)d_out;

    cudaFuncSetAttribute(arc_gemm_kernel,
                         cudaFuncAttributeMaxDynamicSharedMemorySize, SMEM_TOTAL);

    conv_w_kernel<<<(int)(((size_t)NCLS * DIM) / 1024), 256>>>(W);
    prep_x_kernel<<<N_ROWS / 8, 256>>>(x);
    arc_gemm_kernel<<<dim3(MTILES, NTILES), 256, SMEM_TOTAL>>>(target);
    finalize_part_kernel<<<N_ROWS / 512, 512>>>();
    write_out_kernel<<<1, 1>>>(out);
}